// round 1
// baseline (speedup 1.0000x reference)
#include <cuda_runtime.h>
#include <math.h>
#include <stdint.h>

// Problem constants
#define NROWS 8192      // B*T = 4*2048
#define TSEQ  2048
#define DM    1024
#define DFF   2048
#define NHEAD 16
#define DK    64

// ---------------- scratch (static device globals; no allocations) ----------
__device__ float g_x   [NROWS * DM];        // residual stream
__device__ float g_qkv [NROWS * 3 * DM];
__device__ float g_attn[NROWS * DM];
__device__ float g_proj[NROWS * DM];
__device__ float g_ff1 [NROWS * DFF];
__device__ float g_ff2 [NROWS * DM];

// ---------------- embedding + sinusoidal positional encoding ---------------
__global__ __launch_bounds__(256) void embed_pe_kernel(
    const int* __restrict__ tokens, const float* __restrict__ emb,
    float* __restrict__ x)
{
    int row = blockIdx.x;               // 0..8191 (b*2048 + t)
    int tok = tokens[row];
    float tpos = (float)(row & (TSEQ - 1));
    int c = threadIdx.x * 4;
    float4 e = *(const float4*)(emb + (size_t)tok * DM + c);
    float o[4] = {e.x, e.y, e.z, e.w};
    // div[i] = exp(2i * (-ln(10000)/D)); ln(10000)/1024 = 0.00899447301950799
    #pragma unroll
    for (int q = 0; q < 4; q++) {
        int cc = c + q;
        float fi = (float)(cc & ~1);
        float ang = tpos * __expf(fi * -0.00899447301950799f);
        o[q] += (cc & 1) ? cosf(ang) : sinf(ang);
    }
    float4 r; r.x = o[0]; r.y = o[1]; r.z = o[2]; r.w = o[3];
    *(float4*)(x + (size_t)row * DM + c) = r;
}

// ---------------- tiled SGEMM with fused bias (+optional ReLU) -------------
// C[M,N] = A[M,K] @ W[K,N] + bias[N]  (all row-major). M%128==0, N%128==0, K%16==0.
#define BM 128
#define BN 128
#define BK 16
__global__ __launch_bounds__(256) void sgemm_bias(
    const float* __restrict__ A, const float* __restrict__ W,
    const float* __restrict__ bias, float* __restrict__ C,
    int M, int N, int K, int relu)
{
    __shared__ float As[BK][BM];    // A tile, transposed
    __shared__ float Bs[BK][BN];
    int tid = threadIdx.x;
    int rowBase = blockIdx.y * BM;
    int colBase = blockIdx.x * BN;
    int ty = tid >> 4, tx = tid & 15;
    int r0 = ty * 8, c0 = tx * 8;

    float acc[8][8];
    #pragma unroll
    for (int i = 0; i < 8; i++)
        #pragma unroll
        for (int j = 0; j < 8; j++) acc[i][j] = 0.f;

    for (int kt = 0; kt < K; kt += BK) {
        #pragma unroll
        for (int it = 0; it < 2; it++) {
            int p = tid + it * 256;                 // 0..511
            int r  = p >> 2;                        // 0..127
            int k4 = (p & 3) << 2;                  // 0,4,8,12
            float4 va = *(const float4*)(A + (size_t)(rowBase + r) * K + kt + k4);
            As[k4 + 0][r] = va.x; As[k4 + 1][r] = va.y;
            As[k4 + 2][r] = va.z; As[k4 + 3][r] = va.w;
            int br = p >> 5;                        // 0..15
            int bc = (p & 31) << 2;                 // 0..124
            *(float4*)&Bs[br][bc] =
                *(const float4*)(W + (size_t)(kt + br) * N + colBase + bc);
        }
        __syncthreads();
        #pragma unroll
        for (int k = 0; k < BK; k++) {
            float a[8], b[8];
            *(float4*)(a)     = *(const float4*)&As[k][r0];
            *(float4*)(a + 4) = *(const float4*)&As[k][r0 + 4];
            *(float4*)(b)     = *(const float4*)&Bs[k][c0];
            *(float4*)(b + 4) = *(const float4*)&Bs[k][c0 + 4];
            #pragma unroll
            for (int i = 0; i < 8; i++)
                #pragma unroll
                for (int j = 0; j < 8; j++)
                    acc[i][j] = fmaf(a[i], b[j], acc[i][j]);
        }
        __syncthreads();
    }

    #pragma unroll
    for (int i = 0; i < 8; i++) {
        size_t crow = (size_t)(rowBase + r0 + i);
        #pragma unroll
        for (int jj = 0; jj < 8; jj += 4) {
            float4 bv = *(const float4*)(bias + colBase + c0 + jj);
            float4 o;
            o.x = acc[i][jj + 0] + bv.x;
            o.y = acc[i][jj + 1] + bv.y;
            o.z = acc[i][jj + 2] + bv.z;
            o.w = acc[i][jj + 3] + bv.w;
            if (relu) {
                o.x = fmaxf(o.x, 0.f); o.y = fmaxf(o.y, 0.f);
                o.z = fmaxf(o.z, 0.f); o.w = fmaxf(o.w, 0.f);
            }
            *(float4*)(C + crow * N + colBase + c0 + jj) = o;
        }
    }
}

// ---------------- flash attention (fp32, no mask) ---------------------------
// One block = 64 query rows for one (b, h). Online softmax over 2048 keys.
#define ALDS 65
#define ATT_SMEM (4 * 64 * ALDS * 4)
__global__ __launch_bounds__(256) void flash_attn(
    const float* __restrict__ qkv, float* __restrict__ outp)
{
    extern __shared__ float sm[];
    float* Qs = sm;                  // [64][65]
    float* Ks = sm + 64 * ALDS;      // [64][65]
    float* Vs = sm + 2 * 64 * ALDS;  // [64][65]
    float* Ps = sm + 3 * 64 * ALDS;  // [64][65]

    int tid = threadIdx.x;
    int h = blockIdx.y, b = blockIdx.z;
    int qBase = blockIdx.x * 64;
    int btQ = b * TSEQ + qBase;
    int ty = tid >> 4, tx = tid & 15;
    int r0 = ty * 4, c0 = tx * 4;

    // load Q tile (64 x 64)
    #pragma unroll
    for (int it = 0; it < 4; it++) {
        int p = tid + it * 256;
        int r = p >> 4, c4 = (p & 15) << 2;
        float4 v = *(const float4*)(qkv + (size_t)(btQ + r) * (3 * DM) + h * DK + c4);
        Qs[r * ALDS + c4 + 0] = v.x; Qs[r * ALDS + c4 + 1] = v.y;
        Qs[r * ALDS + c4 + 2] = v.z; Qs[r * ALDS + c4 + 3] = v.w;
    }

    float m_run[4], l_run[4], o[4][4];
    #pragma unroll
    for (int i = 0; i < 4; i++) {
        m_run[i] = -1e30f; l_run[i] = 0.f;
        #pragma unroll
        for (int j = 0; j < 4; j++) o[i][j] = 0.f;
    }

    for (int kt = 0; kt < TSEQ; kt += 64) {
        // load K/V tiles
        #pragma unroll
        for (int it = 0; it < 4; it++) {
            int p = tid + it * 256;
            int r = p >> 4, c4 = (p & 15) << 2;
            const float* src = qkv + (size_t)(b * TSEQ + kt + r) * (3 * DM) + h * DK;
            float4 kv = *(const float4*)(src + DM + c4);
            Ks[r * ALDS + c4 + 0] = kv.x; Ks[r * ALDS + c4 + 1] = kv.y;
            Ks[r * ALDS + c4 + 2] = kv.z; Ks[r * ALDS + c4 + 3] = kv.w;
            float4 vv = *(const float4*)(src + 2 * DM + c4);
            Vs[r * ALDS + c4 + 0] = vv.x; Vs[r * ALDS + c4 + 1] = vv.y;
            Vs[r * ALDS + c4 + 2] = vv.z; Vs[r * ALDS + c4 + 3] = vv.w;
        }
        __syncthreads();

        // S = (Q K^T) * 1/sqrt(dk)
        float s[4][4];
        #pragma unroll
        for (int i = 0; i < 4; i++)
            #pragma unroll
            for (int j = 0; j < 4; j++) s[i][j] = 0.f;
        #pragma unroll 8
        for (int k = 0; k < 64; k++) {
            float a[4], bb[4];
            #pragma unroll
            for (int i = 0; i < 4; i++) a[i] = Qs[(r0 + i) * ALDS + k];
            #pragma unroll
            for (int j = 0; j < 4; j++) bb[j] = Ks[(c0 + j) * ALDS + k];
            #pragma unroll
            for (int i = 0; i < 4; i++)
                #pragma unroll
                for (int j = 0; j < 4; j++)
                    s[i][j] = fmaf(a[i], bb[j], s[i][j]);
        }

        // online softmax update (row groups are 16 lane-aligned lanes)
        #pragma unroll
        for (int i = 0; i < 4; i++) {
            #pragma unroll
            for (int j = 0; j < 4; j++) s[i][j] *= 0.125f;  // 1/sqrt(64)
            float mx = fmaxf(fmaxf(s[i][0], s[i][1]), fmaxf(s[i][2], s[i][3]));
            #pragma unroll
            for (int off = 8; off > 0; off >>= 1)
                mx = fmaxf(mx, __shfl_xor_sync(0xffffffffu, mx, off));
            float mn = fmaxf(m_run[i], mx);
            float alpha = __expf(m_run[i] - mn);
            float rs = 0.f;
            #pragma unroll
            for (int j = 0; j < 4; j++) { s[i][j] = __expf(s[i][j] - mn); rs += s[i][j]; }
            #pragma unroll
            for (int off = 8; off > 0; off >>= 1)
                rs += __shfl_xor_sync(0xffffffffu, rs, off);
            l_run[i] = l_run[i] * alpha + rs;
            m_run[i] = mn;
            #pragma unroll
            for (int j = 0; j < 4; j++) {
                o[i][j] *= alpha;
                Ps[(r0 + i) * ALDS + c0 + j] = s[i][j];
            }
        }
        __syncthreads();

        // O += P @ V
        #pragma unroll 8
        for (int kk = 0; kk < 64; kk++) {
            float a[4], bb[4];
            #pragma unroll
            for (int i = 0; i < 4; i++) a[i] = Ps[(r0 + i) * ALDS + kk];
            #pragma unroll
            for (int j = 0; j < 4; j++) bb[j] = Vs[kk * ALDS + c0 + j];
            #pragma unroll
            for (int i = 0; i < 4; i++)
                #pragma unroll
                for (int j = 0; j < 4; j++)
                    o[i][j] = fmaf(a[i], bb[j], o[i][j]);
        }
        __syncthreads();
    }

    #pragma unroll
    for (int i = 0; i < 4; i++) {
        float inv = 1.f / l_run[i];
        float4 ov;
        ov.x = o[i][0] * inv; ov.y = o[i][1] * inv;
        ov.z = o[i][2] * inv; ov.w = o[i][3] * inv;
        *(float4*)(outp + (size_t)(btQ + r0 + i) * DM + h * DK + c0) = ov;
    }
}

// ---------------- fused residual add + LayerNorm ---------------------------
__global__ __launch_bounds__(256) void add_ln_kernel(
    const float* __restrict__ x, const float* __restrict__ y,
    const float* __restrict__ g, const float* __restrict__ b,
    float* __restrict__ outp)
{
    __shared__ float red[8];
    __shared__ float bc;
    int row = blockIdx.x, tid = threadIdx.x;
    int lane = tid & 31, warp = tid >> 5;

    float4 xv = *(const float4*)(x + (size_t)row * DM + tid * 4);
    float4 yv = *(const float4*)(y + (size_t)row * DM + tid * 4);
    float v0 = xv.x + yv.x, v1 = xv.y + yv.y, v2 = xv.z + yv.z, v3 = xv.w + yv.w;

    float s = v0 + v1 + v2 + v3;
    #pragma unroll
    for (int off = 16; off > 0; off >>= 1) s += __shfl_xor_sync(0xffffffffu, s, off);
    if (lane == 0) red[warp] = s;
    __syncthreads();
    if (tid < 8) {
        float t = red[tid];
        #pragma unroll
        for (int off = 4; off > 0; off >>= 1) t += __shfl_xor_sync(0xffu, t, off);
        if (tid == 0) bc = t;
    }
    __syncthreads();
    float mean = bc * (1.f / (float)DM);

    float d0 = v0 - mean, d1 = v1 - mean, d2 = v2 - mean, d3 = v3 - mean;
    float sq = d0 * d0 + d1 * d1 + d2 * d2 + d3 * d3;
    #pragma unroll
    for (int off = 16; off > 0; off >>= 1) sq += __shfl_xor_sync(0xffffffffu, sq, off);
    __syncthreads();                  // protect red/bc reuse
    if (lane == 0) red[warp] = sq;
    __syncthreads();
    if (tid < 8) {
        float t = red[tid];
        #pragma unroll
        for (int off = 4; off > 0; off >>= 1) t += __shfl_xor_sync(0xffu, t, off);
        if (tid == 0) bc = t;
    }
    __syncthreads();
    float rstd = rsqrtf(bc * (1.f / (float)DM) + 1e-5f);

    float4 gv = *(const float4*)(g + tid * 4);
    float4 bv = *(const float4*)(b + tid * 4);
    float4 ov;
    ov.x = d0 * rstd * gv.x + bv.x;
    ov.y = d1 * rstd * gv.y + bv.y;
    ov.z = d2 * rstd * gv.z + bv.z;
    ov.w = d3 * rstd * gv.w + bv.w;
    *(float4*)(outp + (size_t)row * DM + tid * 4) = ov;
}

// ---------------- launcher ---------------------------------------------------
extern "C" void kernel_launch(void* const* d_in, const int* in_sizes, int n_in,
                              void* d_out, int out_size)
{
    (void)in_sizes; (void)n_in; (void)out_size;
    const int*   tokens = (const int*)  d_in[0];
    const float* emb  = (const float*)d_in[1];
    const float* Wqkv = (const float*)d_in[2];
    const float* bqkv = (const float*)d_in[3];
    const float* Wo   = (const float*)d_in[4];
    const float* bo   = (const float*)d_in[5];
    const float* g1   = (const float*)d_in[6];
    const float* be1  = (const float*)d_in[7];
    const float* W1   = (const float*)d_in[8];
    const float* bf1  = (const float*)d_in[9];
    const float* W2   = (const float*)d_in[10];
    const float* bf2  = (const float*)d_in[11];
    const float* g2   = (const float*)d_in[12];
    const float* be2  = (const float*)d_in[13];
    float* outp = (float*)d_out;

    float *x, *qkv, *attn, *proj, *ff1, *ff2;
    cudaGetSymbolAddress((void**)&x,    g_x);
    cudaGetSymbolAddress((void**)&qkv,  g_qkv);
    cudaGetSymbolAddress((void**)&attn, g_attn);
    cudaGetSymbolAddress((void**)&proj, g_proj);
    cudaGetSymbolAddress((void**)&ff1,  g_ff1);
    cudaGetSymbolAddress((void**)&ff2,  g_ff2);

    cudaFuncSetAttribute(flash_attn, cudaFuncAttributeMaxDynamicSharedMemorySize,
                         ATT_SMEM);

    embed_pe_kernel<<<NROWS, 256>>>(tokens, emb, x);

    for (int l = 0; l < 6; ++l) {
        // QKV projection: [8192,1024] @ [1024,3072]
        sgemm_bias<<<dim3(3 * DM / BN, NROWS / BM), 256>>>(
            x, Wqkv + (size_t)l * DM * 3 * DM, bqkv + (size_t)l * 3 * DM,
            qkv, NROWS, 3 * DM, DM, 0);

        // attention
        flash_attn<<<dim3(TSEQ / 64, NHEAD, 4), 256, ATT_SMEM>>>(qkv, attn);

        // output projection
        sgemm_bias<<<dim3(DM / BN, NROWS / BM), 256>>>(
            attn, Wo + (size_t)l * DM * DM, bo + (size_t)l * DM,
            proj, NROWS, DM, DM, 0);

        // x = LN(x + proj)
        add_ln_kernel<<<NROWS, 256>>>(x, proj, g1 + (size_t)l * DM,
                                      be1 + (size_t)l * DM, x);

        // FF1 with ReLU
        sgemm_bias<<<dim3(DFF / BN, NROWS / BM), 256>>>(
            x, W1 + (size_t)l * DM * DFF, bf1 + (size_t)l * DFF,
            ff1, NROWS, DFF, DM, 1);

        // FF2
        sgemm_bias<<<dim3(DM / BN, NROWS / BM), 256>>>(
            ff1, W2 + (size_t)l * DFF * DM, bf2 + (size_t)l * DM,
            ff2, NROWS, DM, DFF, 0);

        // x = LN(x + ff2)  (last layer writes the harness output)
        add_ln_kernel<<<NROWS, 256>>>(x, ff2, g2 + (size_t)l * DM,
                                      be2 + (size_t)l * DM,
                                      (l == 5) ? outp : x);
    }
}

// round 2
// speedup vs baseline: 2.6444x; 2.6444x over previous
#include <cuda_runtime.h>
#include <math.h>
#include <stdint.h>

// Problem constants
#define NROWS 8192      // B*T = 4*2048
#define TSEQ  2048
#define DM    1024
#define DFF   2048
#define NHEAD 16
#define DK    64

// ---------------- scratch (static device globals; no allocations) ----------
__device__ float g_x   [NROWS * DM];
__device__ float g_qkv [NROWS * 3 * DM];
__device__ float g_attn[NROWS * DM];
__device__ float g_proj[NROWS * DM];
__device__ float g_ff1 [NROWS * DFF];
__device__ float g_ff2 [NROWS * DM];

// ---------------- helpers ----------------------------------------------------
__device__ __forceinline__ uint32_t f2tf(float f) {
    uint32_t u;
    asm("cvt.rna.tf32.f32 %0, %1;" : "=r"(u) : "f"(f));
    return u;
}

__device__ __forceinline__ void mma_tf32(
    float& d0, float& d1, float& d2, float& d3,
    uint32_t a0, uint32_t a1, uint32_t a2, uint32_t a3,
    uint32_t b0, uint32_t b1)
{
    asm volatile(
        "mma.sync.aligned.m16n8k8.row.col.f32.tf32.tf32.f32 "
        "{%0,%1,%2,%3},{%4,%5,%6,%7},{%8,%9},{%0,%1,%2,%3};\n"
        : "+f"(d0), "+f"(d1), "+f"(d2), "+f"(d3)
        : "r"(a0), "r"(a1), "r"(a2), "r"(a3), "r"(b0), "r"(b1));
}

// ---------------- embedding + sinusoidal positional encoding ---------------
__global__ __launch_bounds__(256) void embed_pe_kernel(
    const int* __restrict__ tokens, const float* __restrict__ emb,
    float* __restrict__ x)
{
    int row = blockIdx.x;
    int tok = tokens[row];
    float tpos = (float)(row & (TSEQ - 1));
    int c = threadIdx.x * 4;
    float4 e = *(const float4*)(emb + (size_t)tok * DM + c);
    float o[4] = {e.x, e.y, e.z, e.w};
    #pragma unroll
    for (int q = 0; q < 4; q++) {
        int cc = c + q;
        float fi = (float)(cc & ~1);
        float ang = tpos * __expf(fi * -0.00899447301950799f);
        o[q] += (cc & 1) ? cosf(ang) : sinf(ang);
    }
    float4 r; r.x = o[0]; r.y = o[1]; r.z = o[2]; r.w = o[3];
    *(float4*)(x + (size_t)row * DM + c) = r;
}

// ---------------- tf32 tensor-core SGEMM with fused bias (+ReLU) -----------
// C[M,N] = A[M,K] @ W[K,N] + bias[N]. M%128==0, N%128==0, K%16==0.
#define BM 128
#define BN 128
#define BK 16
#define SAST 132   // smem row stride (u32) => stride % 32 == 4 (conflict-free frags)

__global__ __launch_bounds__(256, 2) void sgemm_tf32(
    const float* __restrict__ A, const float* __restrict__ W,
    const float* __restrict__ bias, float* __restrict__ C,
    int M, int N, int K, int relu)
{
    __shared__ uint32_t As[BK][SAST];   // As[k][m] (tf32 bits)
    __shared__ uint32_t Bs[BK][SAST];   // Bs[k][n]

    int tid  = threadIdx.x;
    int warp = tid >> 5, lane = tid & 31;
    int g = lane >> 2, t = lane & 3;
    int wm = warp >> 2;                 // 0..1
    int wn = warp & 3;                  // 0..3
    int rowBase = blockIdx.y * BM;
    int colBase = blockIdx.x * BN;

    float acc[4][4][4];
    #pragma unroll
    for (int i = 0; i < 4; i++)
        #pragma unroll
        for (int j = 0; j < 4; j++)
            #pragma unroll
            for (int r = 0; r < 4; r++) acc[i][j][r] = 0.f;

    // staging indices
    int aIdx0 = tid, aIdx1 = tid + 256;            // 0..511
    int ar0 = aIdx0 >> 2, ak0 = (aIdx0 & 3) << 2;
    int ar1 = aIdx1 >> 2, ak1 = (aIdx1 & 3) << 2;
    int br0 = aIdx0 >> 5, bc0 = (aIdx0 & 31) << 2;
    int br1 = aIdx1 >> 5, bc1 = (aIdx1 & 31) << 2;

    const float* Ab = A + (size_t)rowBase * K;
    const float* Wb = W + colBase;

    float4 ra0 = *(const float4*)(Ab + (size_t)ar0 * K + ak0);
    float4 ra1 = *(const float4*)(Ab + (size_t)ar1 * K + ak1);
    float4 rb0 = *(const float4*)(Wb + (size_t)br0 * N + bc0);
    float4 rb1 = *(const float4*)(Wb + (size_t)br1 * N + bc1);

    for (int kt = 0; kt < K; kt += BK) {
        // store staged tile
        As[ak0 + 0][ar0] = f2tf(ra0.x); As[ak0 + 1][ar0] = f2tf(ra0.y);
        As[ak0 + 2][ar0] = f2tf(ra0.z); As[ak0 + 3][ar0] = f2tf(ra0.w);
        As[ak1 + 0][ar1] = f2tf(ra1.x); As[ak1 + 1][ar1] = f2tf(ra1.y);
        As[ak1 + 2][ar1] = f2tf(ra1.z); As[ak1 + 3][ar1] = f2tf(ra1.w);
        {
            uint4 u0; u0.x = f2tf(rb0.x); u0.y = f2tf(rb0.y);
            u0.z = f2tf(rb0.z); u0.w = f2tf(rb0.w);
            *(uint4*)&Bs[br0][bc0] = u0;
            uint4 u1; u1.x = f2tf(rb1.x); u1.y = f2tf(rb1.y);
            u1.z = f2tf(rb1.z); u1.w = f2tf(rb1.w);
            *(uint4*)&Bs[br1][bc1] = u1;
        }
        __syncthreads();

        if (kt + BK < K) {
            const float* An = Ab + kt + BK;
            const float* Wn = Wb + (size_t)(kt + BK) * N;
            ra0 = *(const float4*)(An + (size_t)ar0 * K + ak0);
            ra1 = *(const float4*)(An + (size_t)ar1 * K + ak1);
            rb0 = *(const float4*)(Wn + (size_t)br0 * N + bc0);
            rb1 = *(const float4*)(Wn + (size_t)br1 * N + bc1);
        }

        #pragma unroll
        for (int ks = 0; ks < BK; ks += 8) {
            uint32_t af[4][4], bf[4][2];
            #pragma unroll
            for (int mt = 0; mt < 4; mt++) {
                int m0 = wm * 64 + mt * 16 + g;
                af[mt][0] = As[ks + t][m0];
                af[mt][1] = As[ks + t][m0 + 8];
                af[mt][2] = As[ks + t + 4][m0];
                af[mt][3] = As[ks + t + 4][m0 + 8];
            }
            #pragma unroll
            for (int nt = 0; nt < 4; nt++) {
                int n0 = wn * 32 + nt * 8 + g;
                bf[nt][0] = Bs[ks + t][n0];
                bf[nt][1] = Bs[ks + t + 4][n0];
            }
            #pragma unroll
            for (int mt = 0; mt < 4; mt++)
                #pragma unroll
                for (int nt = 0; nt < 4; nt++)
                    mma_tf32(acc[mt][nt][0], acc[mt][nt][1],
                             acc[mt][nt][2], acc[mt][nt][3],
                             af[mt][0], af[mt][1], af[mt][2], af[mt][3],
                             bf[nt][0], bf[nt][1]);
        }
        __syncthreads();
    }

    // epilogue: bias (+relu), write f32
    #pragma unroll
    for (int mt = 0; mt < 4; mt++) {
        int r0g = rowBase + wm * 64 + mt * 16 + g;
        #pragma unroll
        for (int nt = 0; nt < 4; nt++) {
            int cc = colBase + wn * 32 + nt * 8 + 2 * t;
            float b0 = bias[cc], b1 = bias[cc + 1];
            float v0 = acc[mt][nt][0] + b0, v1 = acc[mt][nt][1] + b1;
            float v2 = acc[mt][nt][2] + b0, v3 = acc[mt][nt][3] + b1;
            if (relu) {
                v0 = fmaxf(v0, 0.f); v1 = fmaxf(v1, 0.f);
                v2 = fmaxf(v2, 0.f); v3 = fmaxf(v3, 0.f);
            }
            float2 p0; p0.x = v0; p0.y = v1;
            float2 p1; p1.x = v2; p1.y = v3;
            *(float2*)(C + (size_t)r0g * N + cc) = p0;
            *(float2*)(C + (size_t)(r0g + 8) * N + cc) = p1;
        }
    }
}

// ---------------- tf32 tensor-core flash attention ---------------------------
// Block = 64 query rows for one (b,h). 4 warps, each owns 16 query rows.
#define AST 68    // smem row stride (u32): stride % 32 == 4
#define ATT_SMEM_TC (3 * 64 * AST * 4)

__global__ __launch_bounds__(128, 4) void flash_attn_tc(
    const float* __restrict__ qkv, float* __restrict__ outp)
{
    extern __shared__ uint32_t sm[];
    uint32_t* Ks = sm;                // [64][AST]
    uint32_t* Vs = sm + 64 * AST;     // [64][AST]
    uint32_t* QP = sm + 2 * 64 * AST; // Q frags source, then P tile

    int tid = threadIdx.x;
    int w = tid >> 5, lane = tid & 31;
    int g = lane >> 2, t = lane & 3;
    int h = blockIdx.y, b = blockIdx.z;
    int qBase = blockIdx.x * 64;
    int btQ = b * TSEQ + qBase;
    int rl0 = w * 16 + g;             // warp-local query row (and +8)

    // stage Q (64 x 64) as tf32
    #pragma unroll
    for (int it = 0; it < 8; it++) {
        int p = tid + it * 128;
        int r = p >> 4, c4 = (p & 15) << 2;
        float4 v = *(const float4*)(qkv + (size_t)(btQ + r) * (3 * DM) + h * DK + c4);
        uint32_t* dst = QP + r * AST + c4;
        dst[0] = f2tf(v.x); dst[1] = f2tf(v.y);
        dst[2] = f2tf(v.z); dst[3] = f2tf(v.w);
    }
    __syncthreads();

    // extract Q A-fragments (register resident, reused all key tiles)
    uint32_t qa[8][4];
    #pragma unroll
    for (int kt = 0; kt < 8; kt++) {
        qa[kt][0] = QP[rl0 * AST + kt * 8 + t];
        qa[kt][1] = QP[(rl0 + 8) * AST + kt * 8 + t];
        qa[kt][2] = QP[rl0 * AST + kt * 8 + t + 4];
        qa[kt][3] = QP[(rl0 + 8) * AST + kt * 8 + t + 4];
    }

    float o[8][4];
    #pragma unroll
    for (int d = 0; d < 8; d++)
        #pragma unroll
        for (int r = 0; r < 4; r++) o[d][r] = 0.f;
    float m0 = -1e30f, m1 = -1e30f, l0 = 0.f, l1 = 0.f;

    for (int kb = 0; kb < TSEQ; kb += 64) {
        __syncthreads();   // protect Ks/Vs reuse
        #pragma unroll
        for (int it = 0; it < 8; it++) {
            int p = tid + it * 128;
            int r = p >> 4, c4 = (p & 15) << 2;
            const float* src = qkv + (size_t)(b * TSEQ + kb + r) * (3 * DM) + h * DK;
            float4 kv = *(const float4*)(src + DM + c4);
            uint32_t* kd = Ks + r * AST + c4;
            kd[0] = f2tf(kv.x); kd[1] = f2tf(kv.y);
            kd[2] = f2tf(kv.z); kd[3] = f2tf(kv.w);
            float4 vv = *(const float4*)(src + 2 * DM + c4);
            uint32_t* vd = Vs + r * AST + c4;
            vd[0] = f2tf(vv.x); vd[1] = f2tf(vv.y);
            vd[2] = f2tf(vv.z); vd[3] = f2tf(vv.w);
        }
        __syncthreads();

        // S = Q K^T (warp: 16 x 64)
        float s[8][4];
        #pragma unroll
        for (int nt = 0; nt < 8; nt++) {
            s[nt][0] = s[nt][1] = s[nt][2] = s[nt][3] = 0.f;
            #pragma unroll
            for (int kt = 0; kt < 8; kt++) {
                uint32_t b0 = Ks[(nt * 8 + g) * AST + kt * 8 + t];
                uint32_t b1 = Ks[(nt * 8 + g) * AST + kt * 8 + t + 4];
                mma_tf32(s[nt][0], s[nt][1], s[nt][2], s[nt][3],
                         qa[kt][0], qa[kt][1], qa[kt][2], qa[kt][3], b0, b1);
            }
        }

        // online softmax: rows rl0 (regs 0,1) and rl0+8 (regs 2,3)
        float mx0 = -1e30f, mx1 = -1e30f;
        #pragma unroll
        for (int nt = 0; nt < 8; nt++) {
            s[nt][0] *= 0.125f; s[nt][1] *= 0.125f;
            s[nt][2] *= 0.125f; s[nt][3] *= 0.125f;
            mx0 = fmaxf(mx0, fmaxf(s[nt][0], s[nt][1]));
            mx1 = fmaxf(mx1, fmaxf(s[nt][2], s[nt][3]));
        }
        mx0 = fmaxf(mx0, __shfl_xor_sync(0xffffffffu, mx0, 1));
        mx0 = fmaxf(mx0, __shfl_xor_sync(0xffffffffu, mx0, 2));
        mx1 = fmaxf(mx1, __shfl_xor_sync(0xffffffffu, mx1, 1));
        mx1 = fmaxf(mx1, __shfl_xor_sync(0xffffffffu, mx1, 2));
        float nm0 = fmaxf(m0, mx0), nm1 = fmaxf(m1, mx1);
        float al0 = __expf(m0 - nm0), al1 = __expf(m1 - nm1);
        m0 = nm0; m1 = nm1;

        float rs0 = 0.f, rs1 = 0.f;
        #pragma unroll
        for (int nt = 0; nt < 8; nt++) {
            float p0 = __expf(s[nt][0] - m0);
            float p1 = __expf(s[nt][1] - m0);
            float p2 = __expf(s[nt][2] - m1);
            float p3 = __expf(s[nt][3] - m1);
            rs0 += p0 + p1; rs1 += p2 + p3;
            QP[rl0 * AST + nt * 8 + 2 * t]     = f2tf(p0);
            QP[rl0 * AST + nt * 8 + 2 * t + 1] = f2tf(p1);
            QP[(rl0 + 8) * AST + nt * 8 + 2 * t]     = f2tf(p2);
            QP[(rl0 + 8) * AST + nt * 8 + 2 * t + 1] = f2tf(p3);
        }
        rs0 += __shfl_xor_sync(0xffffffffu, rs0, 1);
        rs0 += __shfl_xor_sync(0xffffffffu, rs0, 2);
        rs1 += __shfl_xor_sync(0xffffffffu, rs1, 1);
        rs1 += __shfl_xor_sync(0xffffffffu, rs1, 2);
        l0 = l0 * al0 + rs0;
        l1 = l1 * al1 + rs1;
        #pragma unroll
        for (int d = 0; d < 8; d++) {
            o[d][0] *= al0; o[d][1] *= al0;
            o[d][2] *= al1; o[d][3] *= al1;
        }
        __syncwarp();

        // O += P @ V
        #pragma unroll
        for (int ks = 0; ks < 8; ks++) {
            uint32_t a0 = QP[rl0 * AST + ks * 8 + t];
            uint32_t a1 = QP[(rl0 + 8) * AST + ks * 8 + t];
            uint32_t a2 = QP[rl0 * AST + ks * 8 + t + 4];
            uint32_t a3 = QP[(rl0 + 8) * AST + ks * 8 + t + 4];
            #pragma unroll
            for (int dt = 0; dt < 8; dt++) {
                uint32_t b0 = Vs[(ks * 8 + t) * AST + dt * 8 + g];
                uint32_t b1 = Vs[(ks * 8 + t + 4) * AST + dt * 8 + g];
                mma_tf32(o[dt][0], o[dt][1], o[dt][2], o[dt][3],
                         a0, a1, a2, a3, b0, b1);
            }
        }
    }

    float i0 = 1.f / l0, i1 = 1.f / l1;
    #pragma unroll
    for (int dt = 0; dt < 8; dt++) {
        float2 v0; v0.x = o[dt][0] * i0; v0.y = o[dt][1] * i0;
        float2 v1; v1.x = o[dt][2] * i1; v1.y = o[dt][3] * i1;
        size_t base = (size_t)(btQ + rl0) * DM + h * DK + dt * 8 + 2 * t;
        *(float2*)(outp + base) = v0;
        *(float2*)(outp + base + 8 * DM) = v1;
    }
}

// ---------------- fused residual add + LayerNorm ---------------------------
__global__ __launch_bounds__(256) void add_ln_kernel(
    const float* __restrict__ x, const float* __restrict__ y,
    const float* __restrict__ g, const float* __restrict__ b,
    float* __restrict__ outp)
{
    __shared__ float red[8];
    __shared__ float bc;
    int row = blockIdx.x, tid = threadIdx.x;
    int lane = tid & 31, warp = tid >> 5;

    float4 xv = *(const float4*)(x + (size_t)row * DM + tid * 4);
    float4 yv = *(const float4*)(y + (size_t)row * DM + tid * 4);
    float v0 = xv.x + yv.x, v1 = xv.y + yv.y, v2 = xv.z + yv.z, v3 = xv.w + yv.w;

    float s = v0 + v1 + v2 + v3;
    #pragma unroll
    for (int off = 16; off > 0; off >>= 1) s += __shfl_xor_sync(0xffffffffu, s, off);
    if (lane == 0) red[warp] = s;
    __syncthreads();
    if (tid < 8) {
        float tt = red[tid];
        #pragma unroll
        for (int off = 4; off > 0; off >>= 1) tt += __shfl_xor_sync(0xffu, tt, off);
        if (tid == 0) bc = tt;
    }
    __syncthreads();
    float mean = bc * (1.f / (float)DM);

    float d0 = v0 - mean, d1 = v1 - mean, d2 = v2 - mean, d3 = v3 - mean;
    float sq = d0 * d0 + d1 * d1 + d2 * d2 + d3 * d3;
    #pragma unroll
    for (int off = 16; off > 0; off >>= 1) sq += __shfl_xor_sync(0xffffffffu, sq, off);
    __syncthreads();
    if (lane == 0) red[warp] = sq;
    __syncthreads();
    if (tid < 8) {
        float tt = red[tid];
        #pragma unroll
        for (int off = 4; off > 0; off >>= 1) tt += __shfl_xor_sync(0xffu, tt, off);
        if (tid == 0) bc = tt;
    }
    __syncthreads();
    float rstd = rsqrtf(bc * (1.f / (float)DM) + 1e-5f);

    float4 gv = *(const float4*)(g + tid * 4);
    float4 bv = *(const float4*)(b + tid * 4);
    float4 ov;
    ov.x = d0 * rstd * gv.x + bv.x;
    ov.y = d1 * rstd * gv.y + bv.y;
    ov.z = d2 * rstd * gv.z + bv.z;
    ov.w = d3 * rstd * gv.w + bv.w;
    *(float4*)(outp + (size_t)row * DM + tid * 4) = ov;
}

// ---------------- launcher ---------------------------------------------------
extern "C" void kernel_launch(void* const* d_in, const int* in_sizes, int n_in,
                              void* d_out, int out_size)
{
    (void)in_sizes; (void)n_in; (void)out_size;
    const int*   tokens = (const int*)  d_in[0];
    const float* emb  = (const float*)d_in[1];
    const float* Wqkv = (const float*)d_in[2];
    const float* bqkv = (const float*)d_in[3];
    const float* Wo   = (const float*)d_in[4];
    const float* bo   = (const float*)d_in[5];
    const float* g1   = (const float*)d_in[6];
    const float* be1  = (const float*)d_in[7];
    const float* W1   = (const float*)d_in[8];
    const float* bf1  = (const float*)d_in[9];
    const float* W2   = (const float*)d_in[10];
    const float* bf2  = (const float*)d_in[11];
    const float* g2   = (const float*)d_in[12];
    const float* be2  = (const float*)d_in[13];
    float* outp = (float*)d_out;

    float *x, *qkv, *attn, *proj, *ff1, *ff2;
    cudaGetSymbolAddress((void**)&x,    g_x);
    cudaGetSymbolAddress((void**)&qkv,  g_qkv);
    cudaGetSymbolAddress((void**)&attn, g_attn);
    cudaGetSymbolAddress((void**)&proj, g_proj);
    cudaGetSymbolAddress((void**)&ff1,  g_ff1);
    cudaGetSymbolAddress((void**)&ff2,  g_ff2);

    cudaFuncSetAttribute(flash_attn_tc, cudaFuncAttributeMaxDynamicSharedMemorySize,
                         ATT_SMEM_TC);

    embed_pe_kernel<<<NROWS, 256>>>(tokens, emb, x);

    for (int l = 0; l < 6; ++l) {
        sgemm_tf32<<<dim3(3 * DM / BN, NROWS / BM), 256>>>(
            x, Wqkv + (size_t)l * DM * 3 * DM, bqkv + (size_t)l * 3 * DM,
            qkv, NROWS, 3 * DM, DM, 0);

        flash_attn_tc<<<dim3(TSEQ / 64, NHEAD, 4), 128, ATT_SMEM_TC>>>(qkv, attn);

        sgemm_tf32<<<dim3(DM / BN, NROWS / BM), 256>>>(
            attn, Wo + (size_t)l * DM * DM, bo + (size_t)l * DM,
            proj, NROWS, DM, DM, 0);

        add_ln_kernel<<<NROWS, 256>>>(x, proj, g1 + (size_t)l * DM,
                                      be1 + (size_t)l * DM, x);

        sgemm_tf32<<<dim3(DFF / BN, NROWS / BM), 256>>>(
            x, W1 + (size_t)l * DM * DFF, bf1 + (size_t)l * DFF,
            ff1, NROWS, DFF, DM, 1);

        sgemm_tf32<<<dim3(DM / BN, NROWS / BM), 256>>>(
            ff1, W2 + (size_t)l * DFF * DM, bf2 + (size_t)l * DM,
            ff2, NROWS, DM, DFF, 0);

        add_ln_kernel<<<NROWS, 256>>>(x, ff2, g2 + (size_t)l * DM,
                                      be2 + (size_t)l * DM,
                                      (l == 5) ? outp : x);
    }
}

// round 4
// speedup vs baseline: 3.7101x; 1.4030x over previous
#include <cuda_runtime.h>
#include <math.h>
#include <stdint.h>

// Problem constants
#define NROWS 8192      // B*T
#define TSEQ  2048
#define DM    1024
#define DFF   2048

#define SCALE_QLOG2 0.18033688011112042f   // (1/sqrt(64)) * log2(e)

// ---------------- scratch (static device globals) ---------------------------
__device__ float    g_x   [NROWS * DM];
__device__ uint32_t g_xtf [NROWS * DM];        // tf32 bits of x
__device__ uint32_t g_qkv [NROWS * 3 * DM];    // tf32 bits
__device__ uint32_t g_attn[NROWS * DM];        // tf32 bits
__device__ float    g_proj[NROWS * DM];
__device__ uint32_t g_ff1 [NROWS * DFF];       // tf32 bits (post relu)
__device__ float    g_ff2 [NROWS * DM];

#define WT_QKV 0
#define WT_O   (3072 * 1024)
#define WT_W1  (WT_O + 1024 * 1024)
#define WT_W2  (WT_W1 + 2048 * 1024)
#define WT_LAYER (WT_W2 + 1024 * 2048)
__device__ uint32_t g_wt[6 * WT_LAYER];        // transposed tf32 weights [N][K]
__device__ float    g_bqs[6 * 3072];           // scaled qkv bias

// ---------------- helpers ----------------------------------------------------
__device__ __forceinline__ uint32_t f2tf(float f) {
    uint32_t u;
    asm("cvt.rna.tf32.f32 %0, %1;" : "=r"(u) : "f"(f));
    return u;
}
__device__ __forceinline__ float ex2(float x) {
    float y;
    asm("ex2.approx.f32 %0, %1;" : "=f"(y) : "f"(x));
    return y;
}
__device__ __forceinline__ void mma_tf32(
    float& d0, float& d1, float& d2, float& d3,
    uint32_t a0, uint32_t a1, uint32_t a2, uint32_t a3,
    uint32_t b0, uint32_t b1)
{
    asm volatile(
        "mma.sync.aligned.m16n8k8.row.col.f32.tf32.tf32.f32 "
        "{%0,%1,%2,%3},{%4,%5,%6,%7},{%8,%9},{%0,%1,%2,%3};\n"
        : "+f"(d0), "+f"(d1), "+f"(d2), "+f"(d3)
        : "r"(a0), "r"(a1), "r"(a2), "r"(a3), "r"(b0), "r"(b1));
}
__device__ __forceinline__ uint32_t smem_u32(const void* p) {
    uint32_t a;
    asm("{ .reg .u64 t; cvta.to.shared.u64 t, %1; cvt.u32.u64 %0, t; }"
        : "=r"(a) : "l"(p));
    return a;
}
#define CPA16(dst, src) \
    asm volatile("cp.async.ca.shared.global [%0], [%1], 16;" \
        :: "r"(dst), "l"(src) : "memory")
#define CPA_COMMIT() asm volatile("cp.async.commit_group;" ::: "memory")
#define CPA_WAIT1()  asm volatile("cp.async.wait_group 1;" ::: "memory")
#define CPA_WAIT2()  asm volatile("cp.async.wait_group 2;" ::: "memory")

// ---------------- weight transpose + tf32 round (+ optional row scale) ------
__global__ __launch_bounds__(256) void transpose_cvt(
    const float* __restrict__ W, uint32_t* __restrict__ WT, int K, int N,
    int scale_rows, float scale)
{
    __shared__ float t[32][33];
    int tx = threadIdx.x & 31, ty = threadIdx.x >> 5;
    int bx = blockIdx.x, by = blockIdx.y;
    #pragma unroll
    for (int i = 0; i < 4; i++)
        t[ty + i * 8][tx] = W[(size_t)(by * 32 + ty + i * 8) * N + bx * 32 + tx];
    __syncthreads();
    #pragma unroll
    for (int i = 0; i < 4; i++) {
        int n = bx * 32 + ty + i * 8;
        float v = t[tx][ty + i * 8];
        if (n < scale_rows) v *= scale;
        WT[(size_t)n * K + by * 32 + tx] = f2tf(v);
    }
}

__global__ __launch_bounds__(256) void bias_scale_kernel(
    const float* __restrict__ b, float* __restrict__ o)
{
    int i = blockIdx.x * 256 + threadIdx.x;   // < 6*3072
    float v = b[i];
    o[i] = ((i % 3072) < 1024) ? v * SCALE_QLOG2 : v;
}

// ---------------- embedding + positional encoding (f32 + tf32 copies) ------
__global__ __launch_bounds__(256) void embed_pe_kernel(
    const int* __restrict__ tokens, const float* __restrict__ emb,
    float* __restrict__ x, uint32_t* __restrict__ xtf)
{
    int row = blockIdx.x;
    int tok = tokens[row];
    float tpos = (float)(row & (TSEQ - 1));
    int c = threadIdx.x * 4;
    float4 e = *(const float4*)(emb + (size_t)tok * DM + c);
    float o[4] = {e.x, e.y, e.z, e.w};
    #pragma unroll
    for (int q = 0; q < 4; q++) {
        int cc = c + q;
        float fi = (float)(cc & ~1);
        float ang = tpos * __expf(fi * -0.00899447301950799f);
        o[q] += (cc & 1) ? cosf(ang) : sinf(ang);
    }
    float4 r; r.x = o[0]; r.y = o[1]; r.z = o[2]; r.w = o[3];
    *(float4*)(x + (size_t)row * DM + c) = r;
    uint4 u; u.x = f2tf(o[0]); u.y = f2tf(o[1]); u.z = f2tf(o[2]); u.w = f2tf(o[3]);
    *(uint4*)(xtf + (size_t)row * DM + c) = u;
}

// ---------------- cp.async pipelined HMMA tf32 GEMM -------------------------
// C[M,N] = A[M,K] @ B[N,K]^T + bias. A,B hold tf32 bits. mode: bit0=relu, bit1=tf32-out
#define GST 36
#define GEMM_SMEM (2 * 9216 * 4)

__global__ __launch_bounds__(256, 2) void gemm_cp(
    const uint32_t* __restrict__ A, const uint32_t* __restrict__ B,
    const float* __restrict__ bias, void* __restrict__ Cout,
    int M, int N, int K, int mode)
{
    extern __shared__ uint32_t sg[];
    uint32_t sbase = smem_u32(sg);
    int tid = threadIdx.x, w = tid >> 5, lane = tid & 31;
    int g = lane >> 2, t = lane & 3;
    int wm = w >> 2, wn = w & 3;
    int rowBase = blockIdx.y * 128, colBase = blockIdx.x * 128;

    float acc[4][4][4];
    #pragma unroll
    for (int i = 0; i < 4; i++)
        #pragma unroll
        for (int j = 0; j < 4; j++)
            #pragma unroll
            for (int r = 0; r < 4; r++) acc[i][j][r] = 0.f;

    const int nc = K >> 5;

    // prologue: issue chunks 0,1
    #pragma unroll
    for (int c0 = 0; c0 < 2; ++c0) {
        int kb = c0 * 32;
        uint32_t abase = sbase + (uint32_t)(c0 & 1) * 9216u * 4u;
        uint32_t bbase = abase + 4608u * 4u;
        #pragma unroll
        for (int it = 0; it < 4; ++it) {
            int p = tid + it * 256;
            int r = p >> 3, k4 = (p & 7) << 2;
            CPA16(abase + (uint32_t)(r * GST + k4) * 4u,
                  A + (size_t)(rowBase + r) * K + kb + k4);
            CPA16(bbase + (uint32_t)(r * GST + k4) * 4u,
                  B + (size_t)(colBase + r) * K + kb + k4);
        }
        CPA_COMMIT();
    }

    for (int c = 0; c < nc; ++c) {
        CPA_WAIT1();
        __syncthreads();
        const uint32_t* As = sg + (c & 1) * 9216;
        const uint32_t* Bs = As + 4608;
        #pragma unroll
        for (int ks = 0; ks < 4; ++ks) {
            uint32_t af[4][4], bf[4][2];
            #pragma unroll
            for (int mt = 0; mt < 4; ++mt) {
                int m0 = wm * 64 + mt * 16 + g;
                af[mt][0] = As[m0 * GST + ks * 8 + t];
                af[mt][1] = As[(m0 + 8) * GST + ks * 8 + t];
                af[mt][2] = As[m0 * GST + ks * 8 + t + 4];
                af[mt][3] = As[(m0 + 8) * GST + ks * 8 + t + 4];
            }
            #pragma unroll
            for (int nt = 0; nt < 4; ++nt) {
                int n0 = wn * 32 + nt * 8 + g;
                bf[nt][0] = Bs[n0 * GST + ks * 8 + t];
                bf[nt][1] = Bs[n0 * GST + ks * 8 + t + 4];
            }
            #pragma unroll
            for (int mt = 0; mt < 4; ++mt)
                #pragma unroll
                for (int nt = 0; nt < 4; ++nt)
                    mma_tf32(acc[mt][nt][0], acc[mt][nt][1],
                             acc[mt][nt][2], acc[mt][nt][3],
                             af[mt][0], af[mt][1], af[mt][2], af[mt][3],
                             bf[nt][0], bf[nt][1]);
        }
        __syncthreads();
        int cn = c + 2;
        if (cn < nc) {
            int kb = cn * 32;
            uint32_t abase = sbase + (uint32_t)(cn & 1) * 9216u * 4u;
            uint32_t bbase = abase + 4608u * 4u;
            #pragma unroll
            for (int it = 0; it < 4; ++it) {
                int p = tid + it * 256;
                int r = p >> 3, k4 = (p & 7) << 2;
                CPA16(abase + (uint32_t)(r * GST + k4) * 4u,
                      A + (size_t)(rowBase + r) * K + kb + k4);
                CPA16(bbase + (uint32_t)(r * GST + k4) * 4u,
                      B + (size_t)(colBase + r) * K + kb + k4);
            }
        }
        CPA_COMMIT();
    }

    // epilogue
    int relu = mode & 1, tfout = mode & 2;
    #pragma unroll
    for (int mt = 0; mt < 4; ++mt) {
        int r0g = rowBase + wm * 64 + mt * 16 + g;
        #pragma unroll
        for (int nt = 0; nt < 4; ++nt) {
            int cc = colBase + wn * 32 + nt * 8 + 2 * t;
            float b0 = bias[cc], b1 = bias[cc + 1];
            float v0 = acc[mt][nt][0] + b0, v1 = acc[mt][nt][1] + b1;
            float v2 = acc[mt][nt][2] + b0, v3 = acc[mt][nt][3] + b1;
            if (relu) {
                v0 = fmaxf(v0, 0.f); v1 = fmaxf(v1, 0.f);
                v2 = fmaxf(v2, 0.f); v3 = fmaxf(v3, 0.f);
            }
            if (tfout) {
                uint2 u0; u0.x = f2tf(v0); u0.y = f2tf(v1);
                uint2 u1; u1.x = f2tf(v2); u1.y = f2tf(v3);
                *(uint2*)((uint32_t*)Cout + (size_t)r0g * N + cc) = u0;
                *(uint2*)((uint32_t*)Cout + (size_t)(r0g + 8) * N + cc) = u1;
            } else {
                float2 p0; p0.x = v0; p0.y = v1;
                float2 p1; p1.x = v2; p1.y = v3;
                *(float2*)((float*)Cout + (size_t)r0g * N + cc) = p0;
                *(float2*)((float*)Cout + (size_t)(r0g + 8) * N + cc) = p1;
            }
        }
    }
}

// ---------------- cp.async pipelined flash attention -------------------------
// 256 threads, 128-query tile per (b,h). qkv holds tf32 bits, q pre-scaled
// by (1/sqrt(dk))*log2e so softmax runs in log2 domain.
#define FST 68
#define VST 72
#define P_OFF 0
#define K_OFF (128 * FST)
#define KBUF  (64 * FST)
#define V_OFF (K_OFF + 2 * KBUF)
#define VBUF  (64 * VST)
#define ATT_SMEM ((V_OFF + 2 * VBUF) * 4)

__global__ __launch_bounds__(256, 2) void flash_cp(
    const uint32_t* __restrict__ qkv, uint32_t* __restrict__ attn_tf)
{
    extern __shared__ uint32_t sa[];
    uint32_t sbase = smem_u32(sa);
    int tid = threadIdx.x, w = tid >> 5, lane = tid & 31;
    int g = lane >> 2, t = lane & 3;
    int h = blockIdx.y, b = blockIdx.z;
    int btQ = b * TSEQ + blockIdx.x * 128;
    int rl0 = w * 16 + g;

    // Q prologue into P area
    #pragma unroll
    for (int it = 0; it < 8; ++it) {
        int p = tid + it * 256;
        int r = p >> 4, c4 = (p & 15) << 2;
        CPA16(sbase + (uint32_t)(P_OFF + r * FST + c4) * 4u,
              qkv + (size_t)(btQ + r) * 3072 + h * 64 + c4);
    }
    CPA_COMMIT();

    // KV tiles 0,1
    #pragma unroll
    for (int i0 = 0; i0 < 2; ++i0) {
        #pragma unroll
        for (int it = 0; it < 4; ++it) {
            int p = tid + it * 256;
            int r = p >> 4, c4 = (p & 15) << 2;
            const uint32_t* src = qkv + (size_t)(b * TSEQ + i0 * 64 + r) * 3072 + h * 64;
            CPA16(sbase + (uint32_t)(K_OFF + (i0 & 1) * KBUF + r * FST + c4) * 4u,
                  src + 1024 + c4);
            CPA16(sbase + (uint32_t)(V_OFF + (i0 & 1) * VBUF + r * VST + c4) * 4u,
                  src + 2048 + c4);
        }
        CPA_COMMIT();
    }

    CPA_WAIT2();
    __syncthreads();

    // Q A-fragments (register resident; own warp's rows only)
    uint32_t qa[8][4];
    #pragma unroll
    for (int kt = 0; kt < 8; ++kt) {
        qa[kt][0] = sa[P_OFF + rl0 * FST + kt * 8 + t];
        qa[kt][1] = sa[P_OFF + (rl0 + 8) * FST + kt * 8 + t];
        qa[kt][2] = sa[P_OFF + rl0 * FST + kt * 8 + t + 4];
        qa[kt][3] = sa[P_OFF + (rl0 + 8) * FST + kt * 8 + t + 4];
    }

    float o[8][4];
    #pragma unroll
    for (int d = 0; d < 8; d++)
        #pragma unroll
        for (int r = 0; r < 4; r++) o[d][r] = 0.f;
    float m0 = -1e30f, m1 = -1e30f, l0 = 0.f, l1 = 0.f;
    float* P = (float*)(sa + P_OFF);

    for (int c = 0; c < TSEQ / 64; ++c) {
        CPA_WAIT1();
        __syncthreads();
        const uint32_t* Ks = sa + K_OFF + (c & 1) * KBUF;
        const uint32_t* Vs = sa + V_OFF + (c & 1) * VBUF;

        // S = Qs . K^T  (log2-scaled)
        float s[8][4];
        #pragma unroll
        for (int nt = 0; nt < 8; ++nt) {
            s[nt][0] = s[nt][1] = s[nt][2] = s[nt][3] = 0.f;
            #pragma unroll
            for (int kt = 0; kt < 8; ++kt) {
                uint32_t b0 = Ks[(nt * 8 + g) * FST + kt * 8 + t];
                uint32_t b1 = Ks[(nt * 8 + g) * FST + kt * 8 + t + 4];
                mma_tf32(s[nt][0], s[nt][1], s[nt][2], s[nt][3],
                         qa[kt][0], qa[kt][1], qa[kt][2], qa[kt][3], b0, b1);
            }
        }

        // online softmax (base-2)
        float mx0 = -1e30f, mx1 = -1e30f;
        #pragma unroll
        for (int nt = 0; nt < 8; ++nt) {
            mx0 = fmaxf(mx0, fmaxf(s[nt][0], s[nt][1]));
            mx1 = fmaxf(mx1, fmaxf(s[nt][2], s[nt][3]));
        }
        mx0 = fmaxf(mx0, __shfl_xor_sync(0xffffffffu, mx0, 1));
        mx0 = fmaxf(mx0, __shfl_xor_sync(0xffffffffu, mx0, 2));
        mx1 = fmaxf(mx1, __shfl_xor_sync(0xffffffffu, mx1, 1));
        mx1 = fmaxf(mx1, __shfl_xor_sync(0xffffffffu, mx1, 2));
        float nm0 = fmaxf(m0, mx0), nm1 = fmaxf(m1, mx1);
        float al0 = ex2(m0 - nm0), al1 = ex2(m1 - nm1);
        m0 = nm0; m1 = nm1;

        float rs0 = 0.f, rs1 = 0.f;
        #pragma unroll
        for (int nt = 0; nt < 8; ++nt) {
            float p0 = ex2(s[nt][0] - m0);
            float p1 = ex2(s[nt][1] - m0);
            float p2 = ex2(s[nt][2] - m1);
            float p3 = ex2(s[nt][3] - m1);
            rs0 += p0 + p1; rs1 += p2 + p3;
            float2 q0; q0.x = p0; q0.y = p1;
            float2 q1; q1.x = p2; q1.y = p3;
            *(float2*)(P + rl0 * FST + nt * 8 + 2 * t) = q0;
            *(float2*)(P + (rl0 + 8) * FST + nt * 8 + 2 * t) = q1;
        }
        rs0 += __shfl_xor_sync(0xffffffffu, rs0, 1);
        rs0 += __shfl_xor_sync(0xffffffffu, rs0, 2);
        rs1 += __shfl_xor_sync(0xffffffffu, rs1, 1);
        rs1 += __shfl_xor_sync(0xffffffffu, rs1, 2);
        l0 = l0 * al0 + rs0;
        l1 = l1 * al1 + rs1;
        #pragma unroll
        for (int d = 0; d < 8; d++) {
            o[d][0] *= al0; o[d][1] *= al0;
            o[d][2] *= al1; o[d][3] *= al1;
        }
        __syncwarp();

        // O += P @ V
        #pragma unroll
        for (int ks = 0; ks < 8; ++ks) {
            uint32_t a0 = sa[P_OFF + rl0 * FST + ks * 8 + t];
            uint32_t a1 = sa[P_OFF + (rl0 + 8) * FST + ks * 8 + t];
            uint32_t a2 = sa[P_OFF + rl0 * FST + ks * 8 + t + 4];
            uint32_t a3 = sa[P_OFF + (rl0 + 8) * FST + ks * 8 + t + 4];
            #pragma unroll
            for (int dt = 0; dt < 8; ++dt) {
                uint32_t b0 = Vs[(ks * 8 + t) * VST + dt * 8 + g];
                uint32_t b1 = Vs[(ks * 8 + t + 4) * VST + dt * 8 + g];
                mma_tf32(o[dt][0], o[dt][1], o[dt][2], o[dt][3],
                         a0, a1, a2, a3, b0, b1);
            }
        }
        __syncthreads();

        int cn = c + 2;
        if (cn < TSEQ / 64) {
            #pragma unroll
            for (int it = 0; it < 4; ++it) {
                int p = tid + it * 256;
                int r = p >> 4, c4 = (p & 15) << 2;
                const uint32_t* src = qkv + (size_t)(b * TSEQ + cn * 64 + r) * 3072 + h * 64;
                CPA16(sbase + (uint32_t)(K_OFF + (cn & 1) * KBUF + r * FST + c4) * 4u,
                      src + 1024 + c4);
                CPA16(sbase + (uint32_t)(V_OFF + (cn & 1) * VBUF + r * VST + c4) * 4u,
                      src + 2048 + c4);
            }
        }
        CPA_COMMIT();
    }

    float i0 = 1.f / l0, i1 = 1.f / l1;
    #pragma unroll
    for (int dt = 0; dt < 8; ++dt) {
        uint2 u0; u0.x = f2tf(o[dt][0] * i0); u0.y = f2tf(o[dt][1] * i0);
        uint2 u1; u1.x = f2tf(o[dt][2] * i1); u1.y = f2tf(o[dt][3] * i1);
        size_t base = (size_t)(btQ + rl0) * DM + h * 64 + dt * 8 + 2 * t;
        *(uint2*)(attn_tf + base) = u0;
        *(uint2*)(attn_tf + base + 8 * DM) = u1;
    }
}

// ---------------- fused residual add + LayerNorm (f32 + tf32 outputs) ------
__global__ __launch_bounds__(256) void add_ln_kernel(
    const float* __restrict__ x, const float* __restrict__ y,
    const float* __restrict__ g, const float* __restrict__ b,
    float* __restrict__ outp, uint32_t* __restrict__ otf)
{
    __shared__ float red[8];
    __shared__ float bc;
    int row = blockIdx.x, tid = threadIdx.x;
    int lane = tid & 31, warp = tid >> 5;

    float4 xv = *(const float4*)(x + (size_t)row * DM + tid * 4);
    float4 yv = *(const float4*)(y + (size_t)row * DM + tid * 4);
    float v0 = xv.x + yv.x, v1 = xv.y + yv.y, v2 = xv.z + yv.z, v3 = xv.w + yv.w;

    float s = v0 + v1 + v2 + v3;
    #pragma unroll
    for (int off = 16; off > 0; off >>= 1) s += __shfl_xor_sync(0xffffffffu, s, off);
    if (lane == 0) red[warp] = s;
    __syncthreads();
    if (tid < 8) {
        float tt = red[tid];
        #pragma unroll
        for (int off = 4; off > 0; off >>= 1) tt += __shfl_xor_sync(0xffu, tt, off);
        if (tid == 0) bc = tt;
    }
    __syncthreads();
    float mean = bc * (1.f / (float)DM);

    float d0 = v0 - mean, d1 = v1 - mean, d2 = v2 - mean, d3 = v3 - mean;
    float sq = d0 * d0 + d1 * d1 + d2 * d2 + d3 * d3;
    #pragma unroll
    for (int off = 16; off > 0; off >>= 1) sq += __shfl_xor_sync(0xffffffffu, sq, off);
    __syncthreads();
    if (lane == 0) red[warp] = sq;
    __syncthreads();
    if (tid < 8) {
        float tt = red[tid];
        #pragma unroll
        for (int off = 4; off > 0; off >>= 1) tt += __shfl_xor_sync(0xffu, tt, off);
        if (tid == 0) bc = tt;
    }
    __syncthreads();
    float rstd = rsqrtf(bc * (1.f / (float)DM) + 1e-5f);

    float4 gv = *(const float4*)(g + tid * 4);
    float4 bv = *(const float4*)(b + tid * 4);
    float4 ov;
    ov.x = d0 * rstd * gv.x + bv.x;
    ov.y = d1 * rstd * gv.y + bv.y;
    ov.z = d2 * rstd * gv.z + bv.z;
    ov.w = d3 * rstd * gv.w + bv.w;
    *(float4*)(outp + (size_t)row * DM + tid * 4) = ov;
    uint4 uv; uv.x = f2tf(ov.x); uv.y = f2tf(ov.y);
    uv.z = f2tf(ov.z); uv.w = f2tf(ov.w);
    *(uint4*)(otf + (size_t)row * DM + tid * 4) = uv;
}

// ---------------- launcher ---------------------------------------------------
extern "C" void kernel_launch(void* const* d_in, const int* in_sizes, int n_in,
                              void* d_out, int out_size)
{
    (void)in_sizes; (void)n_in; (void)out_size;
    const int*   tokens = (const int*)  d_in[0];
    const float* emb  = (const float*)d_in[1];
    const float* Wqkv = (const float*)d_in[2];
    const float* bqkv = (const float*)d_in[3];
    const float* Wo   = (const float*)d_in[4];
    const float* bo   = (const float*)d_in[5];
    const float* g1   = (const float*)d_in[6];
    const float* be1  = (const float*)d_in[7];
    const float* W1   = (const float*)d_in[8];
    const float* bf1  = (const float*)d_in[9];
    const float* W2   = (const float*)d_in[10];
    const float* bf2  = (const float*)d_in[11];
    const float* g2   = (const float*)d_in[12];
    const float* be2  = (const float*)d_in[13];
    float* outp = (float*)d_out;

    float *x, *proj, *ff2, *bqs;
    uint32_t *xtf, *qkv, *attn, *ff1, *wt;
    cudaGetSymbolAddress((void**)&x,    g_x);
    cudaGetSymbolAddress((void**)&xtf,  g_xtf);
    cudaGetSymbolAddress((void**)&qkv,  g_qkv);
    cudaGetSymbolAddress((void**)&attn, g_attn);
    cudaGetSymbolAddress((void**)&proj, g_proj);
    cudaGetSymbolAddress((void**)&ff1,  g_ff1);
    cudaGetSymbolAddress((void**)&ff2,  g_ff2);
    cudaGetSymbolAddress((void**)&wt,   g_wt);
    cudaGetSymbolAddress((void**)&bqs,  g_bqs);

    cudaFuncSetAttribute(gemm_cp, cudaFuncAttributeMaxDynamicSharedMemorySize,
                         GEMM_SMEM);
    cudaFuncSetAttribute(flash_cp, cudaFuncAttributeMaxDynamicSharedMemorySize,
                         ATT_SMEM);

    // weight prep: transpose + tf32 round (+q scale folded into Wq, bq)
    for (int l = 0; l < 6; ++l) {
        uint32_t* wl = wt + (size_t)l * WT_LAYER;
        transpose_cvt<<<dim3(3072 / 32, 1024 / 32), 256>>>(
            Wqkv + (size_t)l * DM * 3 * DM, wl + WT_QKV, 1024, 3072,
            1024, SCALE_QLOG2);
        transpose_cvt<<<dim3(1024 / 32, 1024 / 32), 256>>>(
            Wo + (size_t)l * DM * DM, wl + WT_O, 1024, 1024, 0, 1.f);
        transpose_cvt<<<dim3(2048 / 32, 1024 / 32), 256>>>(
            W1 + (size_t)l * DM * DFF, wl + WT_W1, 1024, 2048, 0, 1.f);
        transpose_cvt<<<dim3(1024 / 32, 2048 / 32), 256>>>(
            W2 + (size_t)l * DFF * DM, wl + WT_W2, 2048, 1024, 0, 1.f);
    }
    bias_scale_kernel<<<6 * 3072 / 256, 256>>>(bqkv, bqs);

    embed_pe_kernel<<<NROWS, 256>>>(tokens, emb, x, xtf);

    for (int l = 0; l < 6; ++l) {
        uint32_t* wl = wt + (size_t)l * WT_LAYER;

        // QKV: tf32-bit output (mode 2)
        gemm_cp<<<dim3(3072 / 128, NROWS / 128), 256, GEMM_SMEM>>>(
            xtf, wl + WT_QKV, bqs + (size_t)l * 3072, qkv,
            NROWS, 3 * DM, DM, 2);

        flash_cp<<<dim3(TSEQ / 128, 16, 4), 256, ATT_SMEM>>>(qkv, attn);

        // O projection: f32 output
        gemm_cp<<<dim3(1024 / 128, NROWS / 128), 256, GEMM_SMEM>>>(
            attn, wl + WT_O, bo + (size_t)l * DM, proj,
            NROWS, DM, DM, 0);

        add_ln_kernel<<<NROWS, 256>>>(x, proj, g1 + (size_t)l * DM,
                                      be1 + (size_t)l * DM, x, xtf);

        // FF1: relu + tf32-bit output (mode 3)
        gemm_cp<<<dim3(2048 / 128, NROWS / 128), 256, GEMM_SMEM>>>(
            xtf, wl + WT_W1, bf1 + (size_t)l * DFF, ff1,
            NROWS, DFF, DM, 3);

        // FF2: f32 output
        gemm_cp<<<dim3(1024 / 128, NROWS / 128), 256, GEMM_SMEM>>>(
            ff1, wl + WT_W2, bf2 + (size_t)l * DM, ff2,
            NROWS, DM, DFF, 0);

        add_ln_kernel<<<NROWS, 256>>>(x, ff2, g2 + (size_t)l * DM,
                                      be2 + (size_t)l * DM,
                                      (l == 5) ? outp : x, xtf);
    }
}

// round 6
// speedup vs baseline: 7.1647x; 1.9312x over previous
#include <cuda_runtime.h>
#include <cuda_fp16.h>
#include <math.h>
#include <stdint.h>

// Problem constants
#define NROWS 8192      // B*T
#define TSEQ  2048
#define DM    1024
#define DFF   2048

#define SCALE_QLOG2 0.18033688011112042f   // (1/sqrt(64)) * log2(e)

// ---------------- scratch (static device globals) ---------------------------
__device__ float  g_x   [NROWS * DM];       // f32 residual stream
__device__ __half g_xh  [NROWS * DM];       // half copy of x
__device__ __half g_qkv [NROWS * 3 * DM];   // half qkv (q pre-scaled)
__device__ __half g_attn[NROWS * DM];       // half attention out
__device__ float  g_proj[NROWS * DM];
__device__ __half g_ff1 [NROWS * DFF];      // half, post-relu
__device__ float  g_ff2 [NROWS * DM];

#define WT_QKV 0
#define WT_O   (3072 * 1024)
#define WT_W1  (WT_O + 1024 * 1024)
#define WT_W2  (WT_W1 + 2048 * 1024)
#define WT_LAYER (WT_W2 + 1024 * 2048)
__device__ __half g_wt[6 * WT_LAYER];       // transposed half weights [N][K]
__device__ float  g_bqs[6 * 3072];          // scaled qkv bias

// ---------------- PTX helpers ------------------------------------------------
__device__ __forceinline__ float ex2(float x) {
    float y; asm("ex2.approx.f32 %0, %1;" : "=f"(y) : "f"(x)); return y;
}
__device__ __forceinline__ uint32_t pack_half2(float lo, float hi) {
    uint32_t u;
    asm("cvt.rn.f16x2.f32 %0, %1, %2;" : "=r"(u) : "f"(hi), "f"(lo));
    return u;
}
__device__ __forceinline__ void mma_f16(
    float& d0, float& d1, float& d2, float& d3,
    uint32_t a0, uint32_t a1, uint32_t a2, uint32_t a3,
    uint32_t b0, uint32_t b1)
{
    asm volatile(
        "mma.sync.aligned.m16n8k16.row.col.f32.f16.f16.f32 "
        "{%0,%1,%2,%3},{%4,%5,%6,%7},{%8,%9},{%0,%1,%2,%3};\n"
        : "+f"(d0), "+f"(d1), "+f"(d2), "+f"(d3)
        : "r"(a0), "r"(a1), "r"(a2), "r"(a3), "r"(b0), "r"(b1));
}
__device__ __forceinline__ uint32_t smem_u32(const void* p) {
    uint32_t a;
    asm("{ .reg .u64 t; cvta.to.shared.u64 t, %1; cvt.u32.u64 %0, t; }"
        : "=r"(a) : "l"(p));
    return a;
}
#define LDSM4(R0, R1, R2, R3, ADDR) \
    asm volatile("ldmatrix.sync.aligned.m8n8.x4.shared.b16 {%0,%1,%2,%3}, [%4];" \
        : "=r"(R0), "=r"(R1), "=r"(R2), "=r"(R3) : "r"(ADDR))
#define LDSM4T(R0, R1, R2, R3, ADDR) \
    asm volatile("ldmatrix.sync.aligned.m8n8.x4.trans.shared.b16 {%0,%1,%2,%3}, [%4];" \
        : "=r"(R0), "=r"(R1), "=r"(R2), "=r"(R3) : "r"(ADDR))
#define CPA16(dst, src) \
    asm volatile("cp.async.ca.shared.global [%0], [%1], 16;" \
        :: "r"(dst), "l"(src) : "memory")
#define CPA_COMMIT() asm volatile("cp.async.commit_group;" ::: "memory")
#define CPA_WAIT1()  asm volatile("cp.async.wait_group 1;" ::: "memory")
#define CPA_WAIT2()  asm volatile("cp.async.wait_group 2;" ::: "memory")

// ---------------- weight transpose + half round (+ optional row scale) ------
__global__ __launch_bounds__(256) void transpose_cvt(
    const float* __restrict__ W, __half* __restrict__ WT, int K, int N,
    int scale_rows, float scale)
{
    __shared__ float t[32][33];
    int tx = threadIdx.x & 31, ty = threadIdx.x >> 5;
    int bx = blockIdx.x, by = blockIdx.y;
    #pragma unroll
    for (int i = 0; i < 4; i++)
        t[ty + i * 8][tx] = W[(size_t)(by * 32 + ty + i * 8) * N + bx * 32 + tx];
    __syncthreads();
    #pragma unroll
    for (int i = 0; i < 4; i++) {
        int n = bx * 32 + ty + i * 8;
        float v = t[tx][ty + i * 8];
        if (n < scale_rows) v *= scale;
        WT[(size_t)n * K + by * 32 + tx] = __float2half_rn(v);
    }
}

__global__ __launch_bounds__(256) void bias_scale_kernel(
    const float* __restrict__ b, float* __restrict__ o)
{
    int i = blockIdx.x * 256 + threadIdx.x;
    float v = b[i];
    o[i] = ((i % 3072) < 1024) ? v * SCALE_QLOG2 : v;
}

// ---------------- embedding + positional encoding (f32 + half copies) ------
__global__ __launch_bounds__(256) void embed_pe_kernel(
    const int* __restrict__ tokens, const float* __restrict__ emb,
    float* __restrict__ x, __half* __restrict__ xh)
{
    int row = blockIdx.x;
    int tok = tokens[row];
    float tpos = (float)(row & (TSEQ - 1));
    int c = threadIdx.x * 4;
    float4 e = *(const float4*)(emb + (size_t)tok * DM + c);
    float o[4] = {e.x, e.y, e.z, e.w};
    #pragma unroll
    for (int q = 0; q < 4; q++) {
        int cc = c + q;
        float fi = (float)(cc & ~1);
        float ang = tpos * __expf(fi * -0.00899447301950799f);
        o[q] += (cc & 1) ? cosf(ang) : sinf(ang);
    }
    float4 r; r.x = o[0]; r.y = o[1]; r.z = o[2]; r.w = o[3];
    *(float4*)(x + (size_t)row * DM + c) = r;
    uint2 u; u.x = pack_half2(o[0], o[1]); u.y = pack_half2(o[2], o[3]);
    *(uint2*)(xh + (size_t)row * DM + c) = u;
}

// ---------------- fp16 HMMA GEMM with ldmatrix + 3-stage cp.async -----------
// C[M,N] = A[M,K] @ B[N,K]^T + bias. A,B half. mode: bit0=relu, bit1=half-out
#define GAST 72    // A/B smem row stride (halves) = 144B
#define A_STAGE_H (128 * GAST)
#define B_STAGE_H (256 * GAST)
#define STAGE_H (A_STAGE_H + B_STAGE_H)
#define GEMM_SMEM (3 * STAGE_H * 2)

__global__ __launch_bounds__(256, 1) void gemm_f16(
    const __half* __restrict__ A, const __half* __restrict__ B,
    const float* __restrict__ bias, void* __restrict__ Cout,
    int M, int N, int K, int mode)
{
    extern __shared__ __half sh[];
    uint32_t sbase = smem_u32(sh);
    int tid = threadIdx.x, w = tid >> 5, lane = tid & 31;
    int g = lane >> 2, t = lane & 3;
    int wm = w >> 2, wn = w & 3;                 // warp tile 64x64
    int rowBase = blockIdx.y * 128, colBase = blockIdx.x * 256;

    float acc[4][8][4];
    #pragma unroll
    for (int i = 0; i < 4; i++)
        #pragma unroll
        for (int j = 0; j < 8; j++)
            #pragma unroll
            for (int r = 0; r < 4; r++) acc[i][j][r] = 0.f;

    const int nc = K >> 6;                       // chunks of 64 halves

    // prologue: issue chunks 0..2
    #pragma unroll
    for (int c0 = 0; c0 < 3; ++c0) {
        uint32_t st = sbase + (uint32_t)c0 * (STAGE_H * 2);
        int kb = c0 * 64;
        #pragma unroll
        for (int it = 0; it < 4; ++it) {
            int p = tid + it * 256;
            int r = p >> 3, c8 = (p & 7) * 8;
            CPA16(st + (uint32_t)(r * GAST + c8) * 2u,
                  A + (size_t)(rowBase + r) * K + kb + c8);
        }
        #pragma unroll
        for (int it = 0; it < 8; ++it) {
            int p = tid + it * 256;
            int r = p >> 3, c8 = (p & 7) * 8;
            CPA16(st + (uint32_t)(A_STAGE_H + r * GAST + c8) * 2u,
                  B + (size_t)(colBase + r) * K + kb + c8);
        }
        CPA_COMMIT();
    }

    int lm = lane & 15, lh8 = ((lane >> 4) & 1) * 8;     // A/P addressing
    int bn = (lane & 7) + (((lane >> 4) & 1) * 8);       // B row-within-16
    int bk8 = ((lane >> 3) & 1) * 8;                     // B k lo/hi

    for (int c = 0; c < nc; ++c) {
        CPA_WAIT2();
        __syncthreads();
        uint32_t st = sbase + (uint32_t)(c % 3) * (STAGE_H * 2);
        uint32_t aB = st, bB = st + A_STAGE_H * 2;

        #pragma unroll
        for (int ks = 0; ks < 4; ++ks) {
            uint32_t af[4][4], bf[8][2];
            #pragma unroll
            for (int mt = 0; mt < 4; ++mt) {
                int m0 = wm * 64 + mt * 16;
                uint32_t ad = aB + (uint32_t)((m0 + lm) * GAST + ks * 16 + lh8) * 2u;
                LDSM4(af[mt][0], af[mt][1], af[mt][2], af[mt][3], ad);
            }
            #pragma unroll
            for (int j = 0; j < 4; ++j) {
                int n0 = wn * 64 + j * 16;
                uint32_t bd = bB + (uint32_t)((n0 + bn) * GAST + ks * 16 + bk8) * 2u;
                LDSM4(bf[2*j][0], bf[2*j][1], bf[2*j+1][0], bf[2*j+1][1], bd);
            }
            #pragma unroll
            for (int mt = 0; mt < 4; ++mt)
                #pragma unroll
                for (int nt = 0; nt < 8; ++nt)
                    mma_f16(acc[mt][nt][0], acc[mt][nt][1],
                            acc[mt][nt][2], acc[mt][nt][3],
                            af[mt][0], af[mt][1], af[mt][2], af[mt][3],
                            bf[nt][0], bf[nt][1]);
        }
        __syncthreads();

        int cn = c + 3;
        if (cn < nc) {
            uint32_t s2 = sbase + (uint32_t)(cn % 3) * (STAGE_H * 2);
            int kb = cn * 64;
            #pragma unroll
            for (int it = 0; it < 4; ++it) {
                int p = tid + it * 256;
                int r = p >> 3, c8 = (p & 7) * 8;
                CPA16(s2 + (uint32_t)(r * GAST + c8) * 2u,
                      A + (size_t)(rowBase + r) * K + kb + c8);
            }
            #pragma unroll
            for (int it = 0; it < 8; ++it) {
                int p = tid + it * 256;
                int r = p >> 3, c8 = (p & 7) * 8;
                CPA16(s2 + (uint32_t)(A_STAGE_H + r * GAST + c8) * 2u,
                      B + (size_t)(colBase + r) * K + kb + c8);
            }
        }
        CPA_COMMIT();
    }

    // epilogue
    int relu = mode & 1, hout = mode & 2;
    #pragma unroll
    for (int mt = 0; mt < 4; ++mt) {
        int r0g = rowBase + wm * 64 + mt * 16 + g;
        #pragma unroll
        for (int nt = 0; nt < 8; ++nt) {
            int cc = colBase + wn * 64 + nt * 8 + 2 * t;
            float b0 = bias[cc], b1 = bias[cc + 1];
            float v0 = acc[mt][nt][0] + b0, v1 = acc[mt][nt][1] + b1;
            float v2 = acc[mt][nt][2] + b0, v3 = acc[mt][nt][3] + b1;
            if (relu) {
                v0 = fmaxf(v0, 0.f); v1 = fmaxf(v1, 0.f);
                v2 = fmaxf(v2, 0.f); v3 = fmaxf(v3, 0.f);
            }
            if (hout) {
                *(uint32_t*)((__half*)Cout + (size_t)r0g * N + cc) = pack_half2(v0, v1);
                *(uint32_t*)((__half*)Cout + (size_t)(r0g + 8) * N + cc) = pack_half2(v2, v3);
            } else {
                float2 p0; p0.x = v0; p0.y = v1;
                float2 p1; p1.x = v2; p1.y = v3;
                *(float2*)((float*)Cout + (size_t)r0g * N + cc) = p0;
                *(float2*)((float*)Cout + (size_t)(r0g + 8) * N + cc) = p1;
            }
        }
    }
}

// ---------------- fp16 flash attention with ldmatrix ------------------------
// 256 threads, 8 warps x 16 q-rows = 128 q/CTA. q pre-scaled (log2 softmax).
#define FQST 72                       // Q/P row stride (halves)
#define FKST 72
#define QP_OFF 0                      // 128 x FQST halves
#define FK_OFF (128 * FQST)
#define FKBUF  (64 * FKST)
#define FV_OFF (FK_OFF + 2 * FKBUF)
#define ATT_SMEM ((FV_OFF + 2 * FKBUF) * 2)

__global__ __launch_bounds__(256, 2) void flash_f16(
    const __half* __restrict__ qkv, __half* __restrict__ attn)
{
    extern __shared__ __half sf[];
    uint32_t sbase = smem_u32(sf);
    int tid = threadIdx.x, w = tid >> 5, lane = tid & 31;
    int g = lane >> 2, t = lane & 3;
    int h = blockIdx.y, b = blockIdx.z;
    int btQ = b * TSEQ + blockIdx.x * 128;
    int rl0 = w * 16;
    int lm = lane & 15, lh8 = ((lane >> 4) & 1) * 8;
    int bn = (lane & 7) + (((lane >> 4) & 1) * 8);
    int bk8 = ((lane >> 3) & 1) * 8;

    // Q prologue (group 0)
    #pragma unroll
    for (int it = 0; it < 4; ++it) {
        int p = tid + it * 256;
        int r = p >> 3, c8 = (p & 7) * 8;
        CPA16(sbase + (uint32_t)(QP_OFF + r * FQST + c8) * 2u,
              qkv + (size_t)(btQ + r) * 3072 + h * 64 + c8);
    }
    CPA_COMMIT();

    // K/V tiles 0,1 (groups 1,2)
    #pragma unroll
    for (int i0 = 0; i0 < 2; ++i0) {
        #pragma unroll
        for (int it = 0; it < 2; ++it) {
            int p = tid + it * 256;
            int r = p >> 3, c8 = (p & 7) * 8;
            const __half* src = qkv + (size_t)(b * TSEQ + i0 * 64 + r) * 3072 + h * 64;
            CPA16(sbase + (uint32_t)(FK_OFF + i0 * FKBUF + r * FKST + c8) * 2u,
                  src + 1024 + c8);
            CPA16(sbase + (uint32_t)(FV_OFF + i0 * FKBUF + r * FKST + c8) * 2u,
                  src + 2048 + c8);
        }
        CPA_COMMIT();
    }

    // Q tile was loaded cooperatively by ALL warps: per-thread wait is not
    // enough — need a CTA barrier before cross-warp ldmatrix of Q rows.
    CPA_WAIT2();
    __syncthreads();

    // Q fragments (own warp's 16 rows only)
    uint32_t qa[4][4];
    #pragma unroll
    for (int ks = 0; ks < 4; ++ks) {
        uint32_t ad = sbase + (uint32_t)(QP_OFF + (rl0 + lm) * FQST + ks * 16 + lh8) * 2u;
        LDSM4(qa[ks][0], qa[ks][1], qa[ks][2], qa[ks][3], ad);
    }
    __syncwarp();

    float o[8][4];
    #pragma unroll
    for (int d = 0; d < 8; d++)
        #pragma unroll
        for (int r = 0; r < 4; r++) o[d][r] = 0.f;
    float m0 = -1e30f, m1 = -1e30f, l0 = 0.f, l1 = 0.f;

    for (int c = 0; c < TSEQ / 64; ++c) {
        CPA_WAIT1();
        __syncthreads();
        uint32_t kB = sbase + (uint32_t)(FK_OFF + (c & 1) * FKBUF) * 2u;
        uint32_t vB = sbase + (uint32_t)(FV_OFF + (c & 1) * FKBUF) * 2u;

        // S = Q K^T (warp: 16 x 64)
        float s[8][4];
        #pragma unroll
        for (int nt = 0; nt < 8; ++nt)
            s[nt][0] = s[nt][1] = s[nt][2] = s[nt][3] = 0.f;
        #pragma unroll
        for (int ks = 0; ks < 4; ++ks) {
            uint32_t kf[8][2];
            #pragma unroll
            for (int j = 0; j < 4; ++j) {
                uint32_t kd = kB + (uint32_t)((j * 16 + bn) * FKST + ks * 16 + bk8) * 2u;
                LDSM4(kf[2*j][0], kf[2*j][1], kf[2*j+1][0], kf[2*j+1][1], kd);
            }
            #pragma unroll
            for (int nt = 0; nt < 8; ++nt)
                mma_f16(s[nt][0], s[nt][1], s[nt][2], s[nt][3],
                        qa[ks][0], qa[ks][1], qa[ks][2], qa[ks][3],
                        kf[nt][0], kf[nt][1]);
        }

        // online softmax (base-2)
        float mx0 = -1e30f, mx1 = -1e30f;
        #pragma unroll
        for (int nt = 0; nt < 8; ++nt) {
            mx0 = fmaxf(mx0, fmaxf(s[nt][0], s[nt][1]));
            mx1 = fmaxf(mx1, fmaxf(s[nt][2], s[nt][3]));
        }
        mx0 = fmaxf(mx0, __shfl_xor_sync(0xffffffffu, mx0, 1));
        mx0 = fmaxf(mx0, __shfl_xor_sync(0xffffffffu, mx0, 2));
        mx1 = fmaxf(mx1, __shfl_xor_sync(0xffffffffu, mx1, 1));
        mx1 = fmaxf(mx1, __shfl_xor_sync(0xffffffffu, mx1, 2));
        float nm0 = fmaxf(m0, mx0), nm1 = fmaxf(m1, mx1);
        float al0 = ex2(m0 - nm0), al1 = ex2(m1 - nm1);
        m0 = nm0; m1 = nm1;

        float rs0 = 0.f, rs1 = 0.f;
        __half* P = sf + QP_OFF;
        #pragma unroll
        for (int nt = 0; nt < 8; ++nt) {
            float p0 = ex2(s[nt][0] - m0);
            float p1 = ex2(s[nt][1] - m0);
            float p2 = ex2(s[nt][2] - m1);
            float p3 = ex2(s[nt][3] - m1);
            rs0 += p0 + p1; rs1 += p2 + p3;
            *(uint32_t*)(P + (rl0 + g) * FQST + nt * 8 + 2 * t) = pack_half2(p0, p1);
            *(uint32_t*)(P + (rl0 + 8 + g) * FQST + nt * 8 + 2 * t) = pack_half2(p2, p3);
        }
        rs0 += __shfl_xor_sync(0xffffffffu, rs0, 1);
        rs0 += __shfl_xor_sync(0xffffffffu, rs0, 2);
        rs1 += __shfl_xor_sync(0xffffffffu, rs1, 1);
        rs1 += __shfl_xor_sync(0xffffffffu, rs1, 2);
        l0 = l0 * al0 + rs0;
        l1 = l1 * al1 + rs1;
        #pragma unroll
        for (int d = 0; d < 8; d++) {
            o[d][0] *= al0; o[d][1] *= al0;
            o[d][2] *= al1; o[d][3] *= al1;
        }
        __syncwarp();

        // O += P @ V
        #pragma unroll
        for (int ks = 0; ks < 4; ++ks) {
            uint32_t pa[4];
            uint32_t pd = sbase + (uint32_t)(QP_OFF + (rl0 + lm) * FQST + ks * 16 + lh8) * 2u;
            LDSM4(pa[0], pa[1], pa[2], pa[3], pd);
            uint32_t vf[8][2];
            #pragma unroll
            for (int j = 0; j < 4; ++j) {
                uint32_t vd = vB + (uint32_t)((ks * 16 + lm) * FKST + j * 16 + lh8) * 2u;
                LDSM4T(vf[2*j][0], vf[2*j][1], vf[2*j+1][0], vf[2*j+1][1], vd);
            }
            #pragma unroll
            for (int dt = 0; dt < 8; ++dt)
                mma_f16(o[dt][0], o[dt][1], o[dt][2], o[dt][3],
                        pa[0], pa[1], pa[2], pa[3], vf[dt][0], vf[dt][1]);
        }
        __syncthreads();

        int cn = c + 2;
        if (cn < TSEQ / 64) {
            #pragma unroll
            for (int it = 0; it < 2; ++it) {
                int p = tid + it * 256;
                int r = p >> 3, c8 = (p & 7) * 8;
                const __half* src = qkv + (size_t)(b * TSEQ + cn * 64 + r) * 3072 + h * 64;
                CPA16(sbase + (uint32_t)(FK_OFF + (cn & 1) * FKBUF + r * FKST + c8) * 2u,
                      src + 1024 + c8);
                CPA16(sbase + (uint32_t)(FV_OFF + (cn & 1) * FKBUF + r * FKST + c8) * 2u,
                      src + 2048 + c8);
            }
        }
        CPA_COMMIT();
    }

    float i0 = 1.f / l0, i1 = 1.f / l1;
    #pragma unroll
    for (int dt = 0; dt < 8; ++dt) {
        size_t base = (size_t)(btQ + rl0 + g) * DM + h * 64 + dt * 8 + 2 * t;
        *(uint32_t*)(attn + base) = pack_half2(o[dt][0] * i0, o[dt][1] * i0);
        *(uint32_t*)(attn + base + 8 * DM) = pack_half2(o[dt][2] * i1, o[dt][3] * i1);
    }
}

// ---------------- fused residual add + LayerNorm (f32 + half outputs) ------
__global__ __launch_bounds__(256) void add_ln_kernel(
    const float* __restrict__ x, const float* __restrict__ y,
    const float* __restrict__ g, const float* __restrict__ b,
    float* __restrict__ outp, __half* __restrict__ oh)
{
    __shared__ float red[8];
    __shared__ float bc;
    int row = blockIdx.x, tid = threadIdx.x;
    int lane = tid & 31, warp = tid >> 5;

    float4 xv = *(const float4*)(x + (size_t)row * DM + tid * 4);
    float4 yv = *(const float4*)(y + (size_t)row * DM + tid * 4);
    float v0 = xv.x + yv.x, v1 = xv.y + yv.y, v2 = xv.z + yv.z, v3 = xv.w + yv.w;

    float s = v0 + v1 + v2 + v3;
    #pragma unroll
    for (int off = 16; off > 0; off >>= 1) s += __shfl_xor_sync(0xffffffffu, s, off);
    if (lane == 0) red[warp] = s;
    __syncthreads();
    if (tid < 8) {
        float tt = red[tid];
        #pragma unroll
        for (int off = 4; off > 0; off >>= 1) tt += __shfl_xor_sync(0xffu, tt, off);
        if (tid == 0) bc = tt;
    }
    __syncthreads();
    float mean = bc * (1.f / (float)DM);

    float d0 = v0 - mean, d1 = v1 - mean, d2 = v2 - mean, d3 = v3 - mean;
    float sq = d0 * d0 + d1 * d1 + d2 * d2 + d3 * d3;
    #pragma unroll
    for (int off = 16; off > 0; off >>= 1) sq += __shfl_xor_sync(0xffffffffu, sq, off);
    __syncthreads();
    if (lane == 0) red[warp] = sq;
    __syncthreads();
    if (tid < 8) {
        float tt = red[tid];
        #pragma unroll
        for (int off = 4; off > 0; off >>= 1) tt += __shfl_xor_sync(0xffu, tt, off);
        if (tid == 0) bc = tt;
    }
    __syncthreads();
    float rstd = rsqrtf(bc * (1.f / (float)DM) + 1e-5f);

    float4 gv = *(const float4*)(g + tid * 4);
    float4 bv = *(const float4*)(b + tid * 4);
    float4 ov;
    ov.x = d0 * rstd * gv.x + bv.x;
    ov.y = d1 * rstd * gv.y + bv.y;
    ov.z = d2 * rstd * gv.z + bv.z;
    ov.w = d3 * rstd * gv.w + bv.w;
    *(float4*)(outp + (size_t)row * DM + tid * 4) = ov;
    uint2 u; u.x = pack_half2(ov.x, ov.y); u.y = pack_half2(ov.z, ov.w);
    *(uint2*)(oh + (size_t)row * DM + tid * 4) = u;
}

// ---------------- launcher ---------------------------------------------------
extern "C" void kernel_launch(void* const* d_in, const int* in_sizes, int n_in,
                              void* d_out, int out_size)
{
    (void)in_sizes; (void)n_in; (void)out_size;
    const int*   tokens = (const int*)  d_in[0];
    const float* emb  = (const float*)d_in[1];
    const float* Wqkv = (const float*)d_in[2];
    const float* bqkv = (const float*)d_in[3];
    const float* Wo   = (const float*)d_in[4];
    const float* bo   = (const float*)d_in[5];
    const float* g1   = (const float*)d_in[6];
    const float* be1  = (const float*)d_in[7];
    const float* W1   = (const float*)d_in[8];
    const float* bf1  = (const float*)d_in[9];
    const float* W2   = (const float*)d_in[10];
    const float* bf2  = (const float*)d_in[11];
    const float* g2   = (const float*)d_in[12];
    const float* be2  = (const float*)d_in[13];
    float* outp = (float*)d_out;

    float *x, *proj, *ff2, *bqs;
    __half *xh, *qkv, *attn, *ff1, *wt;
    cudaGetSymbolAddress((void**)&x,    g_x);
    cudaGetSymbolAddress((void**)&xh,   g_xh);
    cudaGetSymbolAddress((void**)&qkv,  g_qkv);
    cudaGetSymbolAddress((void**)&attn, g_attn);
    cudaGetSymbolAddress((void**)&proj, g_proj);
    cudaGetSymbolAddress((void**)&ff1,  g_ff1);
    cudaGetSymbolAddress((void**)&ff2,  g_ff2);
    cudaGetSymbolAddress((void**)&wt,   g_wt);
    cudaGetSymbolAddress((void**)&bqs,  g_bqs);

    cudaFuncSetAttribute(gemm_f16, cudaFuncAttributeMaxDynamicSharedMemorySize,
                         GEMM_SMEM);
    cudaFuncSetAttribute(flash_f16, cudaFuncAttributeMaxDynamicSharedMemorySize,
                         ATT_SMEM);

    for (int l = 0; l < 6; ++l) {
        __half* wl = wt + (size_t)l * WT_LAYER;
        transpose_cvt<<<dim3(3072 / 32, 1024 / 32), 256>>>(
            Wqkv + (size_t)l * DM * 3 * DM, wl + WT_QKV, 1024, 3072,
            1024, SCALE_QLOG2);
        transpose_cvt<<<dim3(1024 / 32, 1024 / 32), 256>>>(
            Wo + (size_t)l * DM * DM, wl + WT_O, 1024, 1024, 0, 1.f);
        transpose_cvt<<<dim3(2048 / 32, 1024 / 32), 256>>>(
            W1 + (size_t)l * DM * DFF, wl + WT_W1, 1024, 2048, 0, 1.f);
        transpose_cvt<<<dim3(1024 / 32, 2048 / 32), 256>>>(
            W2 + (size_t)l * DFF * DM, wl + WT_W2, 2048, 1024, 0, 1.f);
    }
    bias_scale_kernel<<<6 * 3072 / 256, 256>>>(bqkv, bqs);

    embed_pe_kernel<<<NROWS, 256>>>(tokens, emb, x, xh);

    for (int l = 0; l < 6; ++l) {
        __half* wl = wt + (size_t)l * WT_LAYER;

        // QKV: half output (mode 2)
        gemm_f16<<<dim3(3072 / 256, NROWS / 128), 256, GEMM_SMEM>>>(
            xh, wl + WT_QKV, bqs + (size_t)l * 3072, qkv,
            NROWS, 3 * DM, DM, 2);

        flash_f16<<<dim3(TSEQ / 128, 16, 4), 256, ATT_SMEM>>>(qkv, attn);

        // O projection: f32 output
        gemm_f16<<<dim3(1024 / 256, NROWS / 128), 256, GEMM_SMEM>>>(
            attn, wl + WT_O, bo + (size_t)l * DM, proj,
            NROWS, DM, DM, 0);

        add_ln_kernel<<<NROWS, 256>>>(x, proj, g1 + (size_t)l * DM,
                                      be1 + (size_t)l * DM, x, xh);

        // FF1: relu + half output (mode 3)
        gemm_f16<<<dim3(2048 / 256, NROWS / 128), 256, GEMM_SMEM>>>(
            xh, wl + WT_W1, bf1 + (size_t)l * DFF, ff1,
            NROWS, DFF, DM, 3);

        // FF2: f32 output
        gemm_f16<<<dim3(1024 / 256, NROWS / 128), 256, GEMM_SMEM>>>(
            ff1, wl + WT_W2, bf2 + (size_t)l * DM, ff2,
            NROWS, DM, DFF, 0);

        add_ln_kernel<<<NROWS, 256>>>(x, ff2, g2 + (size_t)l * DM,
                                      be2 + (size_t)l * DM,
                                      (l == 5) ? outp : x, xh);
    }
}